// round 16
// baseline (speedup 1.0000x reference)
#include <cuda_runtime.h>
#include <cuda_bf16.h>
#include <cstdint>
#include <math.h>

// Problem constants
#define BB 4
#define SS 2048
#define DD 512
#define HH 8
#define DKK 64
#define FFF 2048
#define MM (BB * SS)   // 8192 rows
#define QKVS 1536      // combined qkv row stride

// ---------------------------------------------------------------------------
// Scratch (device globals — no allocation allowed)
// ---------------------------------------------------------------------------
__device__ float    g_qkv[MM * QKVS];       // q|k|v fp32
__device__ float    g_t1 [MM * DD];         // pre-LN buffer
__device__ float    g_h  [MM * DD];         // post-LN1 fp32 (residual for FFN2)
__device__ uint32_t g_xp_h [MM * 256],  g_xp_m [MM * 256];    // x packed [M][Kp]
__device__ uint32_t g_ctx_h[MM * 256],  g_ctx_m[MM * 256];    // attn out packed
__device__ uint32_t g_hp_h [MM * 256],  g_hp_m [MM * 256];    // h packed
__device__ uint32_t g_ffn_h[MM * 1024], g_ffn_m[MM * 1024];   // ffn hidden packed
// weights packed [Kp][N] hi/mid (round-11 layout)
__device__ uint32_t g_wqkv_h[256 * QKVS], g_wqkv_m[256 * QKVS];
__device__ uint32_t g_wo_h [256 * DD],    g_wo_m [256 * DD];
__device__ uint32_t g_w1_h [256 * FFF],   g_w1_m [256 * FFF];
__device__ uint32_t g_w2_h [1024 * DD],   g_w2_m [1024 * DD];
__device__ float    g_bqkv[QKVS];

// ---------------------------------------------------------------------------
// Helpers
// ---------------------------------------------------------------------------
__device__ __forceinline__ void mma_bf16(float c[4], const uint32_t a[4], const uint32_t b[2]) {
    asm volatile(
        "mma.sync.aligned.m16n8k16.row.col.f32.bf16.bf16.f32 "
        "{%0,%1,%2,%3}, {%4,%5,%6,%7}, {%8,%9}, {%0,%1,%2,%3};"
        : "+f"(c[0]), "+f"(c[1]), "+f"(c[2]), "+f"(c[3])
        : "r"(a[0]), "r"(a[1]), "r"(a[2]), "r"(a[3]), "r"(b[0]), "r"(b[1]));
}

// bf16 hi/mid split of two floats (x -> even k slot, y -> odd k slot)
__device__ __forceinline__ void split_pack(float x, float y, uint32_t& hi, uint32_t& mid) {
    const __nv_bfloat16 hx = __float2bfloat16(x);
    const __nv_bfloat16 hy = __float2bfloat16(y);
    const float rx = x - __bfloat162float(hx);
    const float ry = y - __bfloat162float(hy);
    __nv_bfloat162 h2; h2.x = hx; h2.y = hy;
    __nv_bfloat162 m2; m2.x = __float2bfloat16(rx); m2.y = __float2bfloat16(ry);
    hi  = *reinterpret_cast<uint32_t*>(&h2);
    mid = *reinterpret_cast<uint32_t*>(&m2);
}

// Fragment loaders on packed k-pair words (A: [kp][m], B: [kp][n])
__device__ __forceinline__ void ldaf_w(uint32_t a[4], const uint32_t* base,
                                       int mrow, int lane, int st) {
    const uint32_t* p = base + (lane & 3) * st + mrow + (lane >> 2);
    a[0] = p[0];
    a[1] = p[8];
    a[2] = p[4 * st];
    a[3] = p[4 * st + 8];
}
__device__ __forceinline__ void ldbf_w(uint32_t b[2], const uint32_t* base,
                                       int ncol, int lane, int st) {
    const uint32_t* p = base + (lane & 3) * st + ncol + (lane >> 2);
    b[0] = p[0];
    b[1] = p[4 * st];
}

// ---------------------------------------------------------------------------
// Pack kernels. pack_all covers all six weight matrices in ONE launch so the
// harness's fixed `ncu -s 5 -c 1` lands on a GEMM (launch idx 5 = O-proj).
// ---------------------------------------------------------------------------
__global__ __launch_bounds__(256) void pack_all(
    const float* __restrict__ wq, const float* __restrict__ wk,
    const float* __restrict__ wv, const float* __restrict__ wo,
    const float* __restrict__ w1, const float* __restrict__ w2,
    uint32_t* __restrict__ wqkv_h, uint32_t* __restrict__ wqkv_m,
    uint32_t* __restrict__ wo_h,   uint32_t* __restrict__ wo_m,
    uint32_t* __restrict__ w1_h,   uint32_t* __restrict__ w1_m,
    uint32_t* __restrict__ w2_h,   uint32_t* __restrict__ w2_m)
{
    const int idx = blockIdx.x * 256 + threadIdx.x;
    const float* W; uint32_t *oh, *om;
    int N, ostride, coff, local;
    if (idx < 131072)        { W = wq; oh = wqkv_h; om = wqkv_m; N = 512;  ostride = QKVS; coff = 0;    local = idx; }
    else if (idx < 262144)   { W = wk; oh = wqkv_h; om = wqkv_m; N = 512;  ostride = QKVS; coff = 512;  local = idx - 131072; }
    else if (idx < 393216)   { W = wv; oh = wqkv_h; om = wqkv_m; N = 512;  ostride = QKVS; coff = 1024; local = idx - 262144; }
    else if (idx < 524288)   { W = wo; oh = wo_h;   om = wo_m;   N = 512;  ostride = 512;  coff = 0;    local = idx - 393216; }
    else if (idx < 1048576)  { W = w1; oh = w1_h;   om = w1_m;   N = 2048; ostride = 2048; coff = 0;    local = idx - 524288; }
    else                     { W = w2; oh = w2_h;   om = w2_m;   N = 512;  ostride = 512;  coff = 0;    local = idx - 1048576; }
    const int kp = local / N;
    const int n  = local - kp * N;
    uint32_t h, m;
    split_pack(W[(size_t)(2 * kp) * N + n], W[(size_t)(2 * kp + 1) * N + n], h, m);
    oh[(size_t)kp * ostride + coff + n] = h;
    om[(size_t)kp * ostride + coff + n] = m;
}

__global__ __launch_bounds__(256) void pack_act(
    const float* __restrict__ X, uint32_t* __restrict__ oh, uint32_t* __restrict__ om)
{
    const int idx = blockIdx.x * 256 + threadIdx.x;
    const float4 t = ((const float4*)X)[idx];
    uint32_t h0, m0, h1, m1;
    split_pack(t.x, t.y, h0, m0);
    split_pack(t.z, t.w, h1, m1);
    oh[2 * idx] = h0; oh[2 * idx + 1] = h1;
    om[2 * idx] = m0; om[2 * idx + 1] = m1;
}

__global__ void pack_bias(const float* bq, const float* bk, const float* bv, float* out) {
    const int i = blockIdx.x * 256 + threadIdx.x;
    out[i] = (i < 512) ? bq[i] : (i < 1024) ? bk[i - 512] : bv[i - 1024];
}

// ---------------------------------------------------------------------------
// Packed-operand bf16x3 HMMA GEMM — ROUND-11 EXACT (best measured).
// ---------------------------------------------------------------------------
#define GW 1088
#define STG_W (4 * GW)
#define SMEM_BYTES (2 * STG_W * 4)    // 34816 B

__global__ __launch_bounds__(256, 2) void tc_gemm_p(
    const uint32_t* __restrict__ Ah, const uint32_t* __restrict__ Am,
    const uint32_t* __restrict__ Bh, const uint32_t* __restrict__ Bm,
    const float* __restrict__ bias, const float* __restrict__ resid,
    float* __restrict__ Cf, uint32_t* __restrict__ Ch, uint32_t* __restrict__ Cm,
    int N, int K, int relu)
{
    extern __shared__ uint32_t smu[];
    const int tid  = threadIdx.x;
    const int lane = tid & 31;
    const int wid  = tid >> 5;
    const int m0 = blockIdx.y * 128, n0 = blockIdx.x * 128;
    const int wm = (wid & 1) * 64;
    const int wn = (wid >> 1) * 32;
    const int Kp = K >> 1;

    const int am  = tid & 127;
    const int akp = (tid >> 7) * 4;
    const int bkp = tid >> 5;
    const int bn4 = (tid & 31) * 4;

    float cfr[4][4][4];
#pragma unroll
    for (int t = 0; t < 4; t++)
#pragma unroll
        for (int u = 0; u < 4; u++)
#pragma unroll
            for (int e = 0; e < 4; e++) cfr[t][u][e] = 0.f;

    uint4 aH, aM, bH, bM;
    const int nst = K >> 4;

    aH = *(const uint4*)(Ah + (size_t)(m0 + am) * Kp + akp);
    aM = *(const uint4*)(Am + (size_t)(m0 + am) * Kp + akp);
    bH = *(const uint4*)(Bh + (size_t)bkp * N + n0 + bn4);
    bM = *(const uint4*)(Bm + (size_t)bkp * N + n0 + bn4);
    {
        uint32_t* AH = smu;          uint32_t* AMd = smu + GW;
        uint32_t* BH = smu + 2 * GW; uint32_t* BMd = smu + 3 * GW;
        AH [(akp + 0) * 136 + am] = aH.x;  AMd[(akp + 0) * 136 + am] = aM.x;
        AH [(akp + 1) * 136 + am] = aH.y;  AMd[(akp + 1) * 136 + am] = aM.y;
        AH [(akp + 2) * 136 + am] = aH.z;  AMd[(akp + 2) * 136 + am] = aM.z;
        AH [(akp + 3) * 136 + am] = aH.w;  AMd[(akp + 3) * 136 + am] = aM.w;
        *(uint4*)(BH  + bkp * 136 + bn4) = bH;
        *(uint4*)(BMd + bkp * 136 + bn4) = bM;
    }
    __syncthreads();

    for (int i = 0; i < nst; i++) {
        if (i + 1 < nst) {
            const int kw = (i + 1) << 3;
            aH = *(const uint4*)(Ah + (size_t)(m0 + am) * Kp + kw + akp);
            aM = *(const uint4*)(Am + (size_t)(m0 + am) * Kp + kw + akp);
            bH = *(const uint4*)(Bh + (size_t)(kw + bkp) * N + n0 + bn4);
            bM = *(const uint4*)(Bm + (size_t)(kw + bkp) * N + n0 + bn4);
        }
        {
            const uint32_t* buf = smu + (size_t)(i & 1) * STG_W;
            const uint32_t* AH = buf;          const uint32_t* AMd = buf + GW;
            const uint32_t* BH = buf + 2 * GW; const uint32_t* BMd = buf + 3 * GW;
            uint32_t bh[4][2], bm[4][2];
#pragma unroll
            for (int u = 0; u < 4; u++) {
                ldbf_w(bh[u], BH,  wn + u * 8, lane, 136);
                ldbf_w(bm[u], BMd, wn + u * 8, lane, 136);
            }
#pragma unroll
            for (int t = 0; t < 4; t++) {
                uint32_t ah[4], av[4];
                ldaf_w(ah, AH,  wm + t * 16, lane, 136);
                ldaf_w(av, AMd, wm + t * 16, lane, 136);
#pragma unroll
                for (int u = 0; u < 4; u++) {
                    mma_bf16(cfr[t][u], ah, bh[u]);
                    mma_bf16(cfr[t][u], ah, bm[u]);
                    mma_bf16(cfr[t][u], av, bh[u]);
                }
            }
        }
        if (i + 1 < nst) {
            uint32_t* buf = smu + (size_t)((i + 1) & 1) * STG_W;
            uint32_t* AH = buf;          uint32_t* AMd = buf + GW;
            uint32_t* BH = buf + 2 * GW; uint32_t* BMd = buf + 3 * GW;
            AH [(akp + 0) * 136 + am] = aH.x;  AMd[(akp + 0) * 136 + am] = aM.x;
            AH [(akp + 1) * 136 + am] = aH.y;  AMd[(akp + 1) * 136 + am] = aM.y;
            AH [(akp + 2) * 136 + am] = aH.z;  AMd[(akp + 2) * 136 + am] = aM.z;
            AH [(akp + 3) * 136 + am] = aH.w;  AMd[(akp + 3) * 136 + am] = aM.w;
            *(uint4*)(BH  + bkp * 136 + bn4) = bH;
            *(uint4*)(BMd + bkp * 136 + bn4) = bM;
        }
        __syncthreads();
    }

    const int Np = N >> 1;
#pragma unroll
    for (int t = 0; t < 4; t++) {
        const int r0 = m0 + wm + t * 16 + (lane >> 2);
        const int r1 = r0 + 8;
#pragma unroll
        for (int u = 0; u < 4; u++) {
            const int c = n0 + wn + u * 8 + 2 * (lane & 3);
            const float2 b2 = *(const float2*)(bias + c);
            float o0 = cfr[t][u][0] + b2.x, o1 = cfr[t][u][1] + b2.y;
            float o2 = cfr[t][u][2] + b2.x, o3 = cfr[t][u][3] + b2.y;
            if (relu) {
                o0 = fmaxf(o0, 0.f); o1 = fmaxf(o1, 0.f);
                o2 = fmaxf(o2, 0.f); o3 = fmaxf(o3, 0.f);
            }
            if (resid) {
                const float2 ra = *(const float2*)(resid + (size_t)r0 * N + c);
                const float2 rb = *(const float2*)(resid + (size_t)r1 * N + c);
                o0 += ra.x; o1 += ra.y; o2 += rb.x; o3 += rb.y;
            }
            if (Cf) {
                *(float2*)(Cf + (size_t)r0 * N + c) = make_float2(o0, o1);
                *(float2*)(Cf + (size_t)r1 * N + c) = make_float2(o2, o3);
            }
            if (Ch) {
                const int kpc = c >> 1;
                uint32_t wh, wmid;
                split_pack(o0, o1, wh, wmid);
                Ch[(size_t)r0 * Np + kpc] = wh;  Cm[(size_t)r0 * Np + kpc] = wmid;
                split_pack(o2, o3, wh, wmid);
                Ch[(size_t)r1 * Np + kpc] = wh;  Cm[(size_t)r1 * Np + kpc] = wmid;
            }
        }
    }
}

// ---------------------------------------------------------------------------
// bf16x3 HMMA flash attention, DOUBLE-BUFFERED K/V tiles (gmem loads for tile
// kt+1 staged in registers during tile kt's compute). LJF launch order.
// smem (words): KH 2x1280 @0, KM 2x1280 @2560, VH 2x1152 @5120, VM 2x1152
// @7424, Q/P region 4608 @9728. Total 14336 words = 57344 B.
// ---------------------------------------------------------------------------
#define KT 32
#define WKH 0
#define WKM 2560
#define WVH 5120
#define WVM 7424
#define WQP 9728
#define ATT_SMEM_BYTES (14336 * 4)   // 57344 B

__global__ __launch_bounds__(128) void attn_mma(
    const float* __restrict__ QKV,
    uint32_t* __restrict__ CtxH, uint32_t* __restrict__ CtxM)
{
    extern __shared__ uint32_t smw[];
    const int qb = gridDim.x - 1 - blockIdx.x;   // longest first
    const int h = blockIdx.y, b = blockIdx.z;
    const int tid = threadIdx.x, lane = tid & 31, wid = tid >> 5;

    const float* Q = QKV;
    const float* K = QKV + 512;
    const float* V = QKV + 1024;

    uint32_t* QH  = smw + WQP;
    uint32_t* QMd = smw + WQP + 2304;

    // staging geometry
    const int key = tid & 31, dbK = (tid >> 5) * 16;   // K: 16 dims per thread
    const int vkp = tid >> 4;                          // V: kp base (it adds 8)
    const int d4  = (tid & 15) * 4;

    float4 kr[4], vr0[2], vr1[2];

    // ---- prologue: issue tile-0 gmem loads (latency hidden behind Q prep) ----
    {
        const float* kp_ = K + ((size_t)b * SS + key) * QKVS + h * DKK + dbK;
#pragma unroll
        for (int i = 0; i < 4; i++) kr[i] = *(const float4*)(kp_ + 4 * i);
#pragma unroll
        for (int it = 0; it < 2; it++) {
            const int kp = vkp + it * 8;
            const size_t vb = ((size_t)b * SS + 2 * kp) * QKVS + h * DKK + d4;
            vr0[it] = *(const float4*)(V + vb);
            vr1[it] = *(const float4*)(V + vb + QKVS);
        }
    }

    // ---- Q: transpose + 0.125 scale + split ----
    {
        const int qr = tid & 63;
        const int db = (tid >> 6) * 32;
        const float* qp = Q + ((size_t)b * SS + qb * 64 + qr) * QKVS + h * DKK + db;
#pragma unroll
        for (int i = 0; i < 8; i++) {
            const float4 t = *(const float4*)(qp + 4 * i);
            const int kp = (db + 4 * i) >> 1;
            uint32_t h0, m0w, h1, m1w;
            split_pack(t.x * 0.125f, t.y * 0.125f, h0, m0w);
            split_pack(t.z * 0.125f, t.w * 0.125f, h1, m1w);
            QH [kp * 72 + qr] = h0;        QMd[kp * 72 + qr] = m0w;
            QH [(kp + 1) * 72 + qr] = h1;  QMd[(kp + 1) * 72 + qr] = m1w;
        }
    }
    __syncthreads();

    // ---- Q A-frags into registers ----
    uint32_t qh[4][4], qm[4][4];
    const int q0w = wid * 16;
#pragma unroll
    for (int ks = 0; ks < 4; ks++) {
        ldaf_w(qh[ks], QH  + ks * 8 * 72, q0w, lane, 72);
        ldaf_w(qm[ks], QMd + ks * 8 * 72, q0w, lane, 72);
    }

    // ---- store tile 0 into buffer 0 ----
    {
        uint32_t* KHb = smw + WKH;
        uint32_t* KMb = smw + WKM;
        uint32_t* VHb = smw + WVH;
        uint32_t* VMb = smw + WVM;
#pragma unroll
        for (int i = 0; i < 4; i++) {
            const int kp = (dbK + 4 * i) >> 1;
            uint32_t h0, m0w, h1, m1w;
            split_pack(kr[i].x, kr[i].y, h0, m0w);
            split_pack(kr[i].z, kr[i].w, h1, m1w);
            KHb[kp * 40 + key] = h0;        KMb[kp * 40 + key] = m0w;
            KHb[(kp + 1) * 40 + key] = h1;  KMb[(kp + 1) * 40 + key] = m1w;
        }
#pragma unroll
        for (int it = 0; it < 2; it++) {
            const int kp = vkp + it * 8;
            uint4 hq, mq;
            split_pack(vr0[it].x, vr1[it].x, hq.x, mq.x);
            split_pack(vr0[it].y, vr1[it].y, hq.y, mq.y);
            split_pack(vr0[it].z, vr1[it].z, hq.z, mq.z);
            split_pack(vr0[it].w, vr1[it].w, hq.w, mq.w);
            *(uint4*)(VHb + kp * 72 + d4) = hq;
            *(uint4*)(VMb + kp * 72 + d4) = mq;
        }
    }
    __syncthreads();   // Q frags read by all warps + tile 0 visible

    float o[8][4];
#pragma unroll
    for (int u = 0; u < 8; u++)
#pragma unroll
        for (int e = 0; e < 4; e++) o[u][e] = 0.f;
    float m0 = -1e30f, m1 = -1e30f, l0 = 0.f, l1 = 0.f;

    uint32_t* PH = smw + WQP + wid * 768;
    uint32_t* PM = PH + 384;
    const int r0  = lane >> 2;
    const int ct2 = 2 * (lane & 3);
    const int gq0 = qb * 64 + q0w + r0;

    const int ntk = (qb + 1) * 2;
    for (int kt = 0; kt < ntk; kt++) {
        const int sel = kt & 1;

        // stage tile kt+1 gmem loads (overlap with compute below)
        if (kt + 1 < ntk) {
            const float* kp_ = K + ((size_t)b * SS + (kt + 1) * KT + key) * QKVS + h * DKK + dbK;
#pragma unroll
            for (int i = 0; i < 4; i++) kr[i] = *(const float4*)(kp_ + 4 * i);
#pragma unroll
            for (int it = 0; it < 2; it++) {
                const int kp = vkp + it * 8;
                const size_t vb = ((size_t)b * SS + (kt + 1) * KT + 2 * kp) * QKVS + h * DKK + d4;
                vr0[it] = *(const float4*)(V + vb);
                vr1[it] = *(const float4*)(V + vb + QKVS);
            }
        }

        const uint32_t* KH  = smw + WKH + sel * 1280;
        const uint32_t* KMd = smw + WKM + sel * 1280;
        const uint32_t* VH  = smw + WVH + sel * 1152;
        const uint32_t* VMd = smw + WVM + sel * 1152;

        // ---- S = Q*K^T (bf16x3) ----
        float s[4][4];
#pragma unroll
        for (int u = 0; u < 4; u++)
#pragma unroll
            for (int e = 0; e < 4; e++) s[u][e] = 0.f;
#pragma unroll
        for (int ks = 0; ks < 4; ks++) {
            uint32_t bh[4][2], bm[4][2];
#pragma unroll
            for (int u = 0; u < 4; u++) {
                ldbf_w(bh[u], KH  + ks * 8 * 40, u * 8, lane, 40);
                ldbf_w(bm[u], KMd + ks * 8 * 40, u * 8, lane, 40);
            }
#pragma unroll
            for (int u = 0; u < 4; u++) {
                mma_bf16(s[u], qh[ks], bh[u]);
                mma_bf16(s[u], qh[ks], bm[u]);
                mma_bf16(s[u], qm[ks], bh[u]);
            }
        }

        // ---- causal mask ----
        if (kt * KT + KT - 1 > qb * 64 + q0w) {
#pragma unroll
            for (int u = 0; u < 4; u++) {
                const int c = kt * KT + u * 8 + ct2;
                if (c > gq0)         s[u][0] = -1e30f;
                if (c + 1 > gq0)     s[u][1] = -1e30f;
                if (c > gq0 + 8)     s[u][2] = -1e30f;
                if (c + 1 > gq0 + 8) s[u][3] = -1e30f;
            }
        }
        __syncwarp();

        // ---- online softmax ----
        float rx0 = fmaxf(fmaxf(s[0][0], s[0][1]), fmaxf(s[1][0], s[1][1]));
        rx0 = fmaxf(rx0, fmaxf(fmaxf(s[2][0], s[2][1]), fmaxf(s[3][0], s[3][1])));
        float rx1 = fmaxf(fmaxf(s[0][2], s[0][3]), fmaxf(s[1][2], s[1][3]));
        rx1 = fmaxf(rx1, fmaxf(fmaxf(s[2][2], s[2][3]), fmaxf(s[3][2], s[3][3])));
        rx0 = fmaxf(rx0, __shfl_xor_sync(0xffffffffu, rx0, 1));
        rx0 = fmaxf(rx0, __shfl_xor_sync(0xffffffffu, rx0, 2));
        rx1 = fmaxf(rx1, __shfl_xor_sync(0xffffffffu, rx1, 1));
        rx1 = fmaxf(rx1, __shfl_xor_sync(0xffffffffu, rx1, 2));
        const float mn0 = fmaxf(m0, rx0), mn1 = fmaxf(m1, rx1);
        const float a0 = __expf(m0 - mn0), a1 = __expf(m1 - mn1);
        m0 = mn0; m1 = mn1;

        float ps0 = 0.f, ps1 = 0.f;
#pragma unroll
        for (int u = 0; u < 4; u++) {
            const float p0 = __expf(s[u][0] - m0);
            const float p1 = __expf(s[u][1] - m0);
            const float p2 = __expf(s[u][2] - m1);
            const float p3 = __expf(s[u][3] - m1);
            ps0 += p0 + p1; ps1 += p2 + p3;
            const int kpc = u * 4 + (lane & 3);
            uint32_t hh, mm;
            split_pack(p0, p1, hh, mm);
            PH[kpc * 24 + r0] = hh;      PM[kpc * 24 + r0] = mm;
            split_pack(p2, p3, hh, mm);
            PH[kpc * 24 + r0 + 8] = hh;  PM[kpc * 24 + r0 + 8] = mm;
        }
        ps0 += __shfl_xor_sync(0xffffffffu, ps0, 1);
        ps0 += __shfl_xor_sync(0xffffffffu, ps0, 2);
        ps1 += __shfl_xor_sync(0xffffffffu, ps1, 1);
        ps1 += __shfl_xor_sync(0xffffffffu, ps1, 2);
        l0 = l0 * a0 + ps0;
        l1 = l1 * a1 + ps1;
#pragma unroll
        for (int u = 0; u < 8; u++) {
            o[u][0] *= a0; o[u][1] *= a0; o[u][2] *= a1; o[u][3] *= a1;
        }
        __syncwarp();

        // ---- O += P*V (bf16x3) ----
#pragma unroll
        for (int ks = 0; ks < 2; ks++) {
            uint32_t ah[4], am_[4];
            ldaf_w(ah,  PH + ks * 8 * 24, 0, lane, 24);
            ldaf_w(am_, PM + ks * 8 * 24, 0, lane, 24);
#pragma unroll
            for (int u = 0; u < 8; u++) {
                uint32_t bh2[2], bm2[2];
                ldbf_w(bh2, VH  + ks * 8 * 72, u * 8, lane, 72);
                ldbf_w(bm2, VMd + ks * 8 * 72, u * 8, lane, 72);
                mma_bf16(o[u], ah,  bh2);
                mma_bf16(o[u], ah,  bm2);
                mma_bf16(o[u], am_, bh2);
            }
        }

        // ---- store tile kt+1 into the other buffer ----
        if (kt + 1 < ntk) {
            uint32_t* KHb = smw + WKH + (sel ^ 1) * 1280;
            uint32_t* KMb = smw + WKM + (sel ^ 1) * 1280;
            uint32_t* VHb = smw + WVH + (sel ^ 1) * 1152;
            uint32_t* VMb = smw + WVM + (sel ^ 1) * 1152;
#pragma unroll
            for (int i = 0; i < 4; i++) {
                const int kp = (dbK + 4 * i) >> 1;
                uint32_t h0, m0w, h1, m1w;
                split_pack(kr[i].x, kr[i].y, h0, m0w);
                split_pack(kr[i].z, kr[i].w, h1, m1w);
                KHb[kp * 40 + key] = h0;        KMb[kp * 40 + key] = m0w;
                KHb[(kp + 1) * 40 + key] = h1;  KMb[(kp + 1) * 40 + key] = m1w;
            }
#pragma unroll
            for (int it = 0; it < 2; it++) {
                const int kp = vkp + it * 8;
                uint4 hq, mq;
                split_pack(vr0[it].x, vr1[it].x, hq.x, mq.x);
                split_pack(vr0[it].y, vr1[it].y, hq.y, mq.y);
                split_pack(vr0[it].z, vr1[it].z, hq.z, mq.z);
                split_pack(vr0[it].w, vr1[it].w, hq.w, mq.w);
                *(uint4*)(VHb + kp * 72 + d4) = hq;
                *(uint4*)(VMb + kp * 72 + d4) = mq;
            }
        }
        __syncthreads();
    }

    const float inv0 = 1.f / l0, inv1 = 1.f / l1;
    const size_t row0 = (size_t)b * SS + qb * 64 + q0w + r0;
#pragma unroll
    for (int u = 0; u < 8; u++) {
        const int kpc = (h * DKK + u * 8 + ct2) >> 1;
        uint32_t wh, wm;
        split_pack(o[u][0] * inv0, o[u][1] * inv0, wh, wm);
        CtxH[row0 * 256 + kpc] = wh;       CtxM[row0 * 256 + kpc] = wm;
        split_pack(o[u][2] * inv1, o[u][3] * inv1, wh, wm);
        CtxH[(row0 + 8) * 256 + kpc] = wh; CtxM[(row0 + 8) * 256 + kpc] = wm;
    }
}

// ---------------------------------------------------------------------------
// LayerNorm: warp-per-row, shuffle-only reductions. Optional packed output.
// ---------------------------------------------------------------------------
__global__ __launch_bounds__(256) void ln_warp(
    const float* __restrict__ X, const float* __restrict__ g,
    const float* __restrict__ be, float* __restrict__ out,
    uint32_t* __restrict__ oph, uint32_t* __restrict__ opm)
{
    const int lane = threadIdx.x & 31;
    const int wrp  = threadIdx.x >> 5;
    const int row  = blockIdx.x * 8 + wrp;
    const float4* xp = (const float4*)(X + (size_t)row * DD);

    float4 v[4];
#pragma unroll
    for (int i = 0; i < 4; i++) v[i] = xp[lane + 32 * i];

    float s = 0.f;
#pragma unroll
    for (int i = 0; i < 4; i++) s += (v[i].x + v[i].y) + (v[i].z + v[i].w);
#pragma unroll
    for (int off = 16; off; off >>= 1) s += __shfl_xor_sync(0xffffffffu, s, off);
    const float mu = s * (1.f / DD);

    float q = 0.f;
#pragma unroll
    for (int i = 0; i < 4; i++) {
        const float dx = v[i].x - mu, dy = v[i].y - mu;
        const float dz = v[i].z - mu, dw = v[i].w - mu;
        q += (dx * dx + dy * dy) + (dz * dz + dw * dw);
    }
#pragma unroll
    for (int off = 16; off; off >>= 1) q += __shfl_xor_sync(0xffffffffu, q, off);
    const float rstd = rsqrtf(q * (1.f / DD) + 1e-5f);

#pragma unroll
    for (int i = 0; i < 4; i++) {
        const int c4 = lane + 32 * i;
        const float4 gv = ((const float4*)g)[c4];
        const float4 bv = ((const float4*)be)[c4];
        float4 oo;
        oo.x = (v[i].x - mu) * rstd * gv.x + bv.x;
        oo.y = (v[i].y - mu) * rstd * gv.y + bv.y;
        oo.z = (v[i].z - mu) * rstd * gv.z + bv.z;
        oo.w = (v[i].w - mu) * rstd * gv.w + bv.w;
        ((float4*)(out + (size_t)row * DD))[c4] = oo;
        if (oph) {
            uint32_t h0, m0, h1, m1;
            split_pack(oo.x, oo.y, h0, m0);
            split_pack(oo.z, oo.w, h1, m1);
            oph[(size_t)row * 256 + 2 * c4]     = h0;
            oph[(size_t)row * 256 + 2 * c4 + 1] = h1;
            opm[(size_t)row * 256 + 2 * c4]     = m0;
            opm[(size_t)row * 256 + 2 * c4 + 1] = m1;
        }
    }
}

// ---------------------------------------------------------------------------
// Launch
// ---------------------------------------------------------------------------
static void run_gemm(const uint32_t* Ah, const uint32_t* Am,
                     const uint32_t* Bh, const uint32_t* Bm,
                     const float* bias, const float* resid,
                     float* Cf, uint32_t* Ch, uint32_t* Cm,
                     int M, int N, int K, int relu)
{
    dim3 grid(N / 128, M / 128), block(256);
    tc_gemm_p<<<grid, block, SMEM_BYTES>>>(Ah, Am, Bh, Bm, bias, resid, Cf, Ch, Cm, N, K, relu);
}

extern "C" void kernel_launch(void* const* d_in, const int* in_sizes, int n_in,
                              void* d_out, int out_size)
{
    (void)in_sizes; (void)n_in; (void)out_size;
    const float* x   = (const float*)d_in[0];
    // d_in[1] = mask (deterministic causal tril) — applied analytically
    const float* wq  = (const float*)d_in[2];
    const float* bq  = (const float*)d_in[3];
    const float* wk  = (const float*)d_in[4];
    const float* bk  = (const float*)d_in[5];
    const float* wv  = (const float*)d_in[6];
    const float* bv  = (const float*)d_in[7];
    const float* wo  = (const float*)d_in[8];
    const float* bo  = (const float*)d_in[9];
    const float* w1  = (const float*)d_in[10];
    const float* b1  = (const float*)d_in[11];
    const float* w2  = (const float*)d_in[12];
    const float* b2  = (const float*)d_in[13];
    const float* g1  = (const float*)d_in[14];
    const float* be1 = (const float*)d_in[15];
    const float* g2  = (const float*)d_in[16];
    const float* be2 = (const float*)d_in[17];
    float* out = (float*)d_out;

    float *qkv, *t1, *hbuf, *bqkv;
    uint32_t *xp_h, *xp_m, *ctx_h, *ctx_m, *hp_h, *hp_m, *ffn_h, *ffn_m;
    uint32_t *wqkv_h, *wqkv_m, *wo_h, *wo_m, *w1_h, *w1_m, *w2_h, *w2_m;
    cudaGetSymbolAddress((void**)&qkv,    g_qkv);
    cudaGetSymbolAddress((void**)&t1,     g_t1);
    cudaGetSymbolAddress((void**)&hbuf,   g_h);
    cudaGetSymbolAddress((void**)&bqkv,   g_bqkv);
    cudaGetSymbolAddress((void**)&xp_h,   g_xp_h);
    cudaGetSymbolAddress((void**)&xp_m,   g_xp_m);
    cudaGetSymbolAddress((void**)&ctx_h,  g_ctx_h);
    cudaGetSymbolAddress((void**)&ctx_m,  g_ctx_m);
    cudaGetSymbolAddress((void**)&hp_h,   g_hp_h);
    cudaGetSymbolAddress((void**)&hp_m,   g_hp_m);
    cudaGetSymbolAddress((void**)&ffn_h,  g_ffn_h);
    cudaGetSymbolAddress((void**)&ffn_m,  g_ffn_m);
    cudaGetSymbolAddress((void**)&wqkv_h, g_wqkv_h);
    cudaGetSymbolAddress((void**)&wqkv_m, g_wqkv_m);
    cudaGetSymbolAddress((void**)&wo_h,   g_wo_h);
    cudaGetSymbolAddress((void**)&wo_m,   g_wo_m);
    cudaGetSymbolAddress((void**)&w1_h,   g_w1_h);
    cudaGetSymbolAddress((void**)&w1_m,   g_w1_m);
    cudaGetSymbolAddress((void**)&w2_h,   g_w2_h);
    cudaGetSymbolAddress((void**)&w2_m,   g_w2_m);

    cudaFuncSetAttribute(tc_gemm_p, cudaFuncAttributeMaxDynamicSharedMemorySize, SMEM_BYTES);
    cudaFuncSetAttribute(attn_mma,  cudaFuncAttributeMaxDynamicSharedMemorySize, ATT_SMEM_BYTES);

    // ---- packs: exactly 3 launches so launch idx 5 = O-proj GEMM (ncu -s 5) ----
    pack_all<<<6144, 256>>>(wq, wk, wv, wo, w1, w2,
                            wqkv_h, wqkv_m, wo_h, wo_m, w1_h, w1_m, w2_h, w2_m);
    pack_act<<<(MM * DD / 4) / 256, 256>>>(x, xp_h, xp_m);
    pack_bias<<<QKVS / 256, 256>>>(bq, bk, bv, bqkv);

    // ---- QKV (one combined GEMM, N=1536) ----
    run_gemm(xp_h, xp_m, wqkv_h, wqkv_m, bqkv, nullptr, qkv, nullptr, nullptr,
             MM, QKVS, DD, 0);

    // ---- attention -> packed ctx ----
    attn_mma<<<dim3(SS / 64, HH, BB), 128, ATT_SMEM_BYTES>>>(qkv, ctx_h, ctx_m);

    // ---- O-proj + residual x -> t1; LN1 -> h (fp32 + packed) ----
    run_gemm(ctx_h, ctx_m, wo_h, wo_m, bo, x, t1, nullptr, nullptr, MM, DD, DD, 0);
    ln_warp<<<MM / 8, 256>>>(t1, g1, be1, hbuf, hp_h, hp_m);

    // ---- FFN ----
    run_gemm(hp_h, hp_m, w1_h, w1_m, b1, nullptr, nullptr, ffn_h, ffn_m,
             MM, FFF, DD, 1);
    run_gemm(ffn_h, ffn_m, w2_h, w2_m, b2, hbuf, t1, nullptr, nullptr,
             MM, DD, FFF, 0);
    ln_warp<<<MM / 8, 256>>>(t1, g2, be2, out, nullptr, nullptr);
}

// round 17
// speedup vs baseline: 1.0434x; 1.0434x over previous
#include <cuda_runtime.h>
#include <cuda_bf16.h>
#include <cstdint>
#include <math.h>

// Problem constants
#define BB 4
#define SS 2048
#define DD 512
#define HH 8
#define DKK 64
#define FFF 2048
#define MM (BB * SS)   // 8192 rows
#define QKVS 1536      // combined qkv row stride

// ---------------------------------------------------------------------------
// Scratch (device globals — no allocation allowed)
// ---------------------------------------------------------------------------
__device__ float    g_qkv[MM * QKVS];       // q|k|v fp32
__device__ float    g_t1 [MM * DD];         // pre-LN buffer
__device__ float    g_h  [MM * DD];         // post-LN1 fp32 (residual for FFN2)
__device__ uint32_t g_xp_h [MM * 256],  g_xp_m [MM * 256];    // x packed [M][Kp]
__device__ uint32_t g_ctx_h[MM * 256],  g_ctx_m[MM * 256];    // attn out packed
__device__ uint32_t g_hp_h [MM * 256],  g_hp_m [MM * 256];    // h packed
__device__ uint32_t g_ffn_h[MM * 1024], g_ffn_m[MM * 1024];   // ffn hidden packed
// weights packed [Kp][N] hi/mid
__device__ uint32_t g_wqkv_h[256 * QKVS], g_wqkv_m[256 * QKVS];
__device__ uint32_t g_wo_h [256 * DD],    g_wo_m [256 * DD];
__device__ uint32_t g_w1_h [256 * FFF],   g_w1_m [256 * FFF];
__device__ uint32_t g_w2_h [1024 * DD],   g_w2_m [1024 * DD];
__device__ float    g_bqkv[QKVS];

// ---------------------------------------------------------------------------
// Helpers
// ---------------------------------------------------------------------------
__device__ __forceinline__ void mma_bf16(float c[4], const uint32_t a[4], const uint32_t b[2]) {
    asm volatile(
        "mma.sync.aligned.m16n8k16.row.col.f32.bf16.bf16.f32 "
        "{%0,%1,%2,%3}, {%4,%5,%6,%7}, {%8,%9}, {%0,%1,%2,%3};"
        : "+f"(c[0]), "+f"(c[1]), "+f"(c[2]), "+f"(c[3])
        : "r"(a[0]), "r"(a[1]), "r"(a[2]), "r"(a[3]), "r"(b[0]), "r"(b[1]));
}

// bf16 hi/mid split of two floats (x -> even k slot, y -> odd k slot)
__device__ __forceinline__ void split_pack(float x, float y, uint32_t& hi, uint32_t& mid) {
    const __nv_bfloat16 hx = __float2bfloat16(x);
    const __nv_bfloat16 hy = __float2bfloat16(y);
    const float rx = x - __bfloat162float(hx);
    const float ry = y - __bfloat162float(hy);
    __nv_bfloat162 h2; h2.x = hx; h2.y = hy;
    __nv_bfloat162 m2; m2.x = __float2bfloat16(rx); m2.y = __float2bfloat16(ry);
    hi  = *reinterpret_cast<uint32_t*>(&h2);
    mid = *reinterpret_cast<uint32_t*>(&m2);
}

// Fragment loaders on packed k-pair words (A: [kp][m], B: [kp][n])
__device__ __forceinline__ void ldaf_w(uint32_t a[4], const uint32_t* base,
                                       int mrow, int lane, int st) {
    const uint32_t* p = base + (lane & 3) * st + mrow + (lane >> 2);
    a[0] = p[0];
    a[1] = p[8];
    a[2] = p[4 * st];
    a[3] = p[4 * st + 8];
}
__device__ __forceinline__ void ldbf_w(uint32_t b[2], const uint32_t* base,
                                       int ncol, int lane, int st) {
    const uint32_t* p = base + (lane & 3) * st + ncol + (lane >> 2);
    b[0] = p[0];
    b[1] = p[4 * st];
}

// ---------------------------------------------------------------------------
// Pack kernels (3 launches total so the fixed ncu -s lands on a GEMM)
// ---------------------------------------------------------------------------
__global__ __launch_bounds__(256) void pack_all(
    const float* __restrict__ wq, const float* __restrict__ wk,
    const float* __restrict__ wv, const float* __restrict__ wo,
    const float* __restrict__ w1, const float* __restrict__ w2,
    uint32_t* __restrict__ wqkv_h, uint32_t* __restrict__ wqkv_m,
    uint32_t* __restrict__ wo_h,   uint32_t* __restrict__ wo_m,
    uint32_t* __restrict__ w1_h,   uint32_t* __restrict__ w1_m,
    uint32_t* __restrict__ w2_h,   uint32_t* __restrict__ w2_m)
{
    const int idx = blockIdx.x * 256 + threadIdx.x;
    const float* W; uint32_t *oh, *om;
    int N, ostride, coff, local;
    if (idx < 131072)        { W = wq; oh = wqkv_h; om = wqkv_m; N = 512;  ostride = QKVS; coff = 0;    local = idx; }
    else if (idx < 262144)   { W = wk; oh = wqkv_h; om = wqkv_m; N = 512;  ostride = QKVS; coff = 512;  local = idx - 131072; }
    else if (idx < 393216)   { W = wv; oh = wqkv_h; om = wqkv_m; N = 512;  ostride = QKVS; coff = 1024; local = idx - 262144; }
    else if (idx < 524288)   { W = wo; oh = wo_h;   om = wo_m;   N = 512;  ostride = 512;  coff = 0;    local = idx - 393216; }
    else if (idx < 1048576)  { W = w1; oh = w1_h;   om = w1_m;   N = 2048; ostride = 2048; coff = 0;    local = idx - 524288; }
    else                     { W = w2; oh = w2_h;   om = w2_m;   N = 512;  ostride = 512;  coff = 0;    local = idx - 1048576; }
    const int kp = local / N;
    const int n  = local - kp * N;
    uint32_t h, m;
    split_pack(W[(size_t)(2 * kp) * N + n], W[(size_t)(2 * kp + 1) * N + n], h, m);
    oh[(size_t)kp * ostride + coff + n] = h;
    om[(size_t)kp * ostride + coff + n] = m;
}

__global__ __launch_bounds__(256) void pack_act(
    const float* __restrict__ X, uint32_t* __restrict__ oh, uint32_t* __restrict__ om)
{
    const int idx = blockIdx.x * 256 + threadIdx.x;
    const float4 t = ((const float4*)X)[idx];
    uint32_t h0, m0, h1, m1;
    split_pack(t.x, t.y, h0, m0);
    split_pack(t.z, t.w, h1, m1);
    oh[2 * idx] = h0; oh[2 * idx + 1] = h1;
    om[2 * idx] = m0; om[2 * idx + 1] = m1;
}

__global__ void pack_bias(const float* bq, const float* bk, const float* bv, float* out) {
    const int i = blockIdx.x * 256 + threadIdx.x;
    out[i] = (i < 512) ? bq[i] : (i < 1024) ? bk[i - 512] : bv[i - 1024];
}

// ---------------------------------------------------------------------------
// Packed bf16x3 HMMA GEMM, 64x128 CTA tile, 3 CTAs/SM (RF-occupancy fix).
// A: packed [M][Kp] hi/mid. B: packed [Kp][N] hi/mid.
// 256 threads, 8 warps as 2m x 4n of 32x32 warp tiles. BK=16 (8 kp/stage).
// smem per stage (words): AH[8][72], AM[8][72], BH[8][136], BM[8][136].
// A stride 72 (=8 mod 32): frag LDS conflict-free (same proof as 136).
// ---------------------------------------------------------------------------
#define AW 576                         // 8*72
#define BW 1088                        // 8*136
#define STGW (2 * AW + 2 * BW)         // 3328 words
#define SMEM_BYTES (2 * STGW * 4)      // 26624 B

__global__ __launch_bounds__(256, 3) void tc_gemm_p(
    const uint32_t* __restrict__ Ah, const uint32_t* __restrict__ Am,
    const uint32_t* __restrict__ Bh, const uint32_t* __restrict__ Bm,
    const float* __restrict__ bias, const float* __restrict__ resid,
    float* __restrict__ Cf, uint32_t* __restrict__ Ch, uint32_t* __restrict__ Cm,
    int N, int K, int relu)
{
    extern __shared__ uint32_t smu[];
    const int tid  = threadIdx.x;
    const int lane = tid & 31;
    const int wid  = tid >> 5;
    const int m0 = blockIdx.y * 64, n0 = blockIdx.x * 128;
    const int wm = (wid & 1) * 32;
    const int wn = (wid >> 1) * 32;
    const int Kp = K >> 1;

    const int arow = tid >> 2;          // 0..63 A row within tile
    const int akq  = (tid & 3) << 1;    // A kp word base (0/2/4/6), uint2
    const int bkp  = tid >> 5;          // B kp row (0..7)
    const int bn4  = (tid & 31) * 4;    // B col group

    float cfr[2][4][4];
#pragma unroll
    for (int t = 0; t < 2; t++)
#pragma unroll
        for (int u = 0; u < 4; u++)
#pragma unroll
            for (int e = 0; e < 4; e++) cfr[t][u][e] = 0.f;

    uint2 aH2, aM2;
    uint4 bH, bM;
    const int nst = K >> 4;

    // stage 0 load + store
    aH2 = *(const uint2*)(Ah + (size_t)(m0 + arow) * Kp + akq);
    aM2 = *(const uint2*)(Am + (size_t)(m0 + arow) * Kp + akq);
    bH  = *(const uint4*)(Bh + (size_t)bkp * N + n0 + bn4);
    bM  = *(const uint4*)(Bm + (size_t)bkp * N + n0 + bn4);
    {
        uint32_t* AH = smu;          uint32_t* AMd = smu + AW;
        uint32_t* BH = smu + 2 * AW; uint32_t* BMd = smu + 2 * AW + BW;
        AH [(akq + 0) * 72 + arow] = aH2.x;  AMd[(akq + 0) * 72 + arow] = aM2.x;
        AH [(akq + 1) * 72 + arow] = aH2.y;  AMd[(akq + 1) * 72 + arow] = aM2.y;
        *(uint4*)(BH  + bkp * 136 + bn4) = bH;
        *(uint4*)(BMd + bkp * 136 + bn4) = bM;
    }
    __syncthreads();

    for (int i = 0; i < nst; i++) {
        if (i + 1 < nst) {
            const int kw = (i + 1) << 3;
            aH2 = *(const uint2*)(Ah + (size_t)(m0 + arow) * Kp + kw + akq);
            aM2 = *(const uint2*)(Am + (size_t)(m0 + arow) * Kp + kw + akq);
            bH  = *(const uint4*)(Bh + (size_t)(kw + bkp) * N + n0 + bn4);
            bM  = *(const uint4*)(Bm + (size_t)(kw + bkp) * N + n0 + bn4);
        }
        {
            const uint32_t* buf = smu + (size_t)(i & 1) * STGW;
            const uint32_t* AH = buf;          const uint32_t* AMd = buf + AW;
            const uint32_t* BH = buf + 2 * AW; const uint32_t* BMd = buf + 2 * AW + BW;
            uint32_t bh[4][2], bm[4][2];
#pragma unroll
            for (int u = 0; u < 4; u++) {
                ldbf_w(bh[u], BH,  wn + u * 8, lane, 136);
                ldbf_w(bm[u], BMd, wn + u * 8, lane, 136);
            }
#pragma unroll
            for (int t = 0; t < 2; t++) {
                uint32_t ah[4], av[4];
                ldaf_w(ah, AH,  wm + t * 16, lane, 72);
                ldaf_w(av, AMd, wm + t * 16, lane, 72);
#pragma unroll
                for (int u = 0; u < 4; u++) {
                    mma_bf16(cfr[t][u], ah, bh[u]);
                    mma_bf16(cfr[t][u], ah, bm[u]);
                    mma_bf16(cfr[t][u], av, bh[u]);
                }
            }
        }
        if (i + 1 < nst) {
            uint32_t* buf = smu + (size_t)((i + 1) & 1) * STGW;
            uint32_t* AH = buf;          uint32_t* AMd = buf + AW;
            uint32_t* BH = buf + 2 * AW; uint32_t* BMd = buf + 2 * AW + BW;
            AH [(akq + 0) * 72 + arow] = aH2.x;  AMd[(akq + 0) * 72 + arow] = aM2.x;
            AH [(akq + 1) * 72 + arow] = aH2.y;  AMd[(akq + 1) * 72 + arow] = aM2.y;
            *(uint4*)(BH  + bkp * 136 + bn4) = bH;
            *(uint4*)(BMd + bkp * 136 + bn4) = bM;
        }
        __syncthreads();
    }

    // ---- epilogue ----
    const int Np = N >> 1;
#pragma unroll
    for (int t = 0; t < 2; t++) {
        const int r0 = m0 + wm + t * 16 + (lane >> 2);
        const int r1 = r0 + 8;
#pragma unroll
        for (int u = 0; u < 4; u++) {
            const int c = n0 + wn + u * 8 + 2 * (lane & 3);
            const float2 b2 = *(const float2*)(bias + c);
            float o0 = cfr[t][u][0] + b2.x, o1 = cfr[t][u][1] + b2.y;
            float o2 = cfr[t][u][2] + b2.x, o3 = cfr[t][u][3] + b2.y;
            if (relu) {
                o0 = fmaxf(o0, 0.f); o1 = fmaxf(o1, 0.f);
                o2 = fmaxf(o2, 0.f); o3 = fmaxf(o3, 0.f);
            }
            if (resid) {
                const float2 ra = *(const float2*)(resid + (size_t)r0 * N + c);
                const float2 rb = *(const float2*)(resid + (size_t)r1 * N + c);
                o0 += ra.x; o1 += ra.y; o2 += rb.x; o3 += rb.y;
            }
            if (Cf) {
                *(float2*)(Cf + (size_t)r0 * N + c) = make_float2(o0, o1);
                *(float2*)(Cf + (size_t)r1 * N + c) = make_float2(o2, o3);
            }
            if (Ch) {
                const int kpc = c >> 1;
                uint32_t wh, wmid;
                split_pack(o0, o1, wh, wmid);
                Ch[(size_t)r0 * Np + kpc] = wh;  Cm[(size_t)r0 * Np + kpc] = wmid;
                split_pack(o2, o3, wh, wmid);
                Ch[(size_t)r1 * Np + kpc] = wh;  Cm[(size_t)r1 * Np + kpc] = wmid;
            }
        }
    }
}

// ---------------------------------------------------------------------------
// bf16x3 HMMA flash attention — round-15 version (single-buffered; the
// double-buffered round-16 variant measured slower). LJF launch order.
// ---------------------------------------------------------------------------
#define KT 32
#define WKH 0
#define WKM 1280
#define WVH 2560
#define WVM 3712
#define WQH 4864
#define WQM 7168
#define ATT_SMEM_BYTES (9472 * 4)   // 37888 B

__global__ __launch_bounds__(128) void attn_mma(
    const float* __restrict__ QKV,
    uint32_t* __restrict__ CtxH, uint32_t* __restrict__ CtxM)
{
    extern __shared__ uint32_t smw[];
    const int qb = gridDim.x - 1 - blockIdx.x;   // longest first
    const int h = blockIdx.y, b = blockIdx.z;
    const int tid = threadIdx.x, lane = tid & 31, wid = tid >> 5;

    const float* Q = QKV;
    const float* K = QKV + 512;
    const float* V = QKV + 1024;

    uint32_t* KH = smw + WKH;
    uint32_t* KMd = smw + WKM;
    uint32_t* VH = smw + WVH;
    uint32_t* VMd = smw + WVM;
    uint32_t* QH = smw + WQH;
    uint32_t* QMd = smw + WQM;

    {
        const int qr = tid & 63;
        const int db = (tid >> 6) * 32;
        const float* qp = Q + ((size_t)b * SS + qb * 64 + qr) * QKVS + h * DKK + db;
#pragma unroll
        for (int i = 0; i < 8; i++) {
            const float4 t = *(const float4*)(qp + 4 * i);
            const int kp = (db + 4 * i) >> 1;
            uint32_t h0, m0w, h1, m1w;
            split_pack(t.x * 0.125f, t.y * 0.125f, h0, m0w);
            split_pack(t.z * 0.125f, t.w * 0.125f, h1, m1w);
            QH [kp * 72 + qr] = h0;        QMd[kp * 72 + qr] = m0w;
            QH [(kp + 1) * 72 + qr] = h1;  QMd[(kp + 1) * 72 + qr] = m1w;
        }
    }
    __syncthreads();

    uint32_t qh[4][4], qm[4][4];
    const int q0w = wid * 16;
#pragma unroll
    for (int ks = 0; ks < 4; ks++) {
        ldaf_w(qh[ks], QH  + ks * 8 * 72, q0w, lane, 72);
        ldaf_w(qm[ks], QMd + ks * 8 * 72, q0w, lane, 72);
    }
    __syncthreads();

    float o[8][4];
#pragma unroll
    for (int u = 0; u < 8; u++)
#pragma unroll
        for (int e = 0; e < 4; e++) o[u][e] = 0.f;
    float m0 = -1e30f, m1 = -1e30f, l0 = 0.f, l1 = 0.f;

    uint32_t* PH = smw + WQH + wid * 768;
    uint32_t* PM = PH + 384;
    const int r0  = lane >> 2;
    const int ct2 = 2 * (lane & 3);
    const int gq0 = qb * 64 + q0w + r0;

    const int ntk = (qb + 1) * 2;
    for (int kt = 0; kt < ntk; kt++) {
        __syncthreads();
        {
            const int key = tid & 31, db = (tid >> 5) * 16;
            const float* kp_ = K + ((size_t)b * SS + kt * KT + key) * QKVS + h * DKK + db;
#pragma unroll
            for (int i = 0; i < 4; i++) {
                const float4 t = *(const float4*)(kp_ + 4 * i);
                const int kp = (db + 4 * i) >> 1;
                uint32_t h0, m0w, h1, m1w;
                split_pack(t.x, t.y, h0, m0w);
                split_pack(t.z, t.w, h1, m1w);
                KH [kp * 40 + key] = h0;        KMd[kp * 40 + key] = m0w;
                KH [(kp + 1) * 40 + key] = h1;  KMd[(kp + 1) * 40 + key] = m1w;
            }
        }
        {
#pragma unroll
            for (int it = 0; it < 2; it++) {
                const int kp = (tid >> 4) + it * 8;
                const int d4 = (tid & 15) * 4;
                const size_t vb = ((size_t)b * SS + kt * KT + 2 * kp) * QKVS + h * DKK + d4;
                const float4 v0 = *(const float4*)(V + vb);
                const float4 v1 = *(const float4*)(V + vb + QKVS);
                uint4 hq, mq;
                split_pack(v0.x, v1.x, hq.x, mq.x);
                split_pack(v0.y, v1.y, hq.y, mq.y);
                split_pack(v0.z, v1.z, hq.z, mq.z);
                split_pack(v0.w, v1.w, hq.w, mq.w);
                *(uint4*)(VH  + kp * 72 + d4) = hq;
                *(uint4*)(VMd + kp * 72 + d4) = mq;
            }
        }
        __syncthreads();

        float s[4][4];
#pragma unroll
        for (int u = 0; u < 4; u++)
#pragma unroll
            for (int e = 0; e < 4; e++) s[u][e] = 0.f;
#pragma unroll
        for (int ks = 0; ks < 4; ks++) {
            uint32_t bh[4][2], bm[4][2];
#pragma unroll
            for (int u = 0; u < 4; u++) {
                ldbf_w(bh[u], KH  + ks * 8 * 40, u * 8, lane, 40);
                ldbf_w(bm[u], KMd + ks * 8 * 40, u * 8, lane, 40);
            }
#pragma unroll
            for (int u = 0; u < 4; u++) {
                mma_bf16(s[u], qh[ks], bh[u]);
                mma_bf16(s[u], qh[ks], bm[u]);
                mma_bf16(s[u], qm[ks], bh[u]);
            }
        }

        if (kt * KT + KT - 1 > qb * 64 + q0w) {
#pragma unroll
            for (int u = 0; u < 4; u++) {
                const int c = kt * KT + u * 8 + ct2;
                if (c > gq0)         s[u][0] = -1e30f;
                if (c + 1 > gq0)     s[u][1] = -1e30f;
                if (c > gq0 + 8)     s[u][2] = -1e30f;
                if (c + 1 > gq0 + 8) s[u][3] = -1e30f;
            }
        }
        __syncwarp();

        float rx0 = fmaxf(fmaxf(s[0][0], s[0][1]), fmaxf(s[1][0], s[1][1]));
        rx0 = fmaxf(rx0, fmaxf(fmaxf(s[2][0], s[2][1]), fmaxf(s[3][0], s[3][1])));
        float rx1 = fmaxf(fmaxf(s[0][2], s[0][3]), fmaxf(s[1][2], s[1][3]));
        rx1 = fmaxf(rx1, fmaxf(fmaxf(s[2][2], s[2][3]), fmaxf(s[3][2], s[3][3])));
        rx0 = fmaxf(rx0, __shfl_xor_sync(0xffffffffu, rx0, 1));
        rx0 = fmaxf(rx0, __shfl_xor_sync(0xffffffffu, rx0, 2));
        rx1 = fmaxf(rx1, __shfl_xor_sync(0xffffffffu, rx1, 1));
        rx1 = fmaxf(rx1, __shfl_xor_sync(0xffffffffu, rx1, 2));
        const float mn0 = fmaxf(m0, rx0), mn1 = fmaxf(m1, rx1);
        const float a0 = __expf(m0 - mn0), a1 = __expf(m1 - mn1);
        m0 = mn0; m1 = mn1;

        float ps0 = 0.f, ps1 = 0.f;
#pragma unroll
        for (int u = 0; u < 4; u++) {
            const float p0 = __expf(s[u][0] - m0);
            const float p1 = __expf(s[u][1] - m0);
            const float p2 = __expf(s[u][2] - m1);
            const float p3 = __expf(s[u][3] - m1);
            ps0 += p0 + p1; ps1 += p2 + p3;
            const int kpc = u * 4 + (lane & 3);
            uint32_t hh, mm;
            split_pack(p0, p1, hh, mm);
            PH[kpc * 24 + r0] = hh;      PM[kpc * 24 + r0] = mm;
            split_pack(p2, p3, hh, mm);
            PH[kpc * 24 + r0 + 8] = hh;  PM[kpc * 24 + r0 + 8] = mm;
        }
        ps0 += __shfl_xor_sync(0xffffffffu, ps0, 1);
        ps0 += __shfl_xor_sync(0xffffffffu, ps0, 2);
        ps1 += __shfl_xor_sync(0xffffffffu, ps1, 1);
        ps1 += __shfl_xor_sync(0xffffffffu, ps1, 2);
        l0 = l0 * a0 + ps0;
        l1 = l1 * a1 + ps1;
#pragma unroll
        for (int u = 0; u < 8; u++) {
            o[u][0] *= a0; o[u][1] *= a0; o[u][2] *= a1; o[u][3] *= a1;
        }
        __syncwarp();

#pragma unroll
        for (int ks = 0; ks < 2; ks++) {
            uint32_t ah[4], am_[4];
            ldaf_w(ah,  PH + ks * 8 * 24, 0, lane, 24);
            ldaf_w(am_, PM + ks * 8 * 24, 0, lane, 24);
#pragma unroll
            for (int u = 0; u < 8; u++) {
                uint32_t bh2[2], bm2[2];
                ldbf_w(bh2, VH  + ks * 8 * 72, u * 8, lane, 72);
                ldbf_w(bm2, VMd + ks * 8 * 72, u * 8, lane, 72);
                mma_bf16(o[u], ah,  bh2);
                mma_bf16(o[u], ah,  bm2);
                mma_bf16(o[u], am_, bh2);
            }
        }
    }

    const float inv0 = 1.f / l0, inv1 = 1.f / l1;
    const size_t row0 = (size_t)b * SS + qb * 64 + q0w + r0;
#pragma unroll
    for (int u = 0; u < 8; u++) {
        const int kpc = (h * DKK + u * 8 + ct2) >> 1;
        uint32_t wh, wm;
        split_pack(o[u][0] * inv0, o[u][1] * inv0, wh, wm);
        CtxH[row0 * 256 + kpc] = wh;       CtxM[row0 * 256 + kpc] = wm;
        split_pack(o[u][2] * inv1, o[u][3] * inv1, wh, wm);
        CtxH[(row0 + 8) * 256 + kpc] = wh; CtxM[(row0 + 8) * 256 + kpc] = wm;
    }
}

// ---------------------------------------------------------------------------
// LayerNorm: warp-per-row, shuffle-only reductions. Optional packed output.
// ---------------------------------------------------------------------------
__global__ __launch_bounds__(256) void ln_warp(
    const float* __restrict__ X, const float* __restrict__ g,
    const float* __restrict__ be, float* __restrict__ out,
    uint32_t* __restrict__ oph, uint32_t* __restrict__ opm)
{
    const int lane = threadIdx.x & 31;
    const int wrp  = threadIdx.x >> 5;
    const int row  = blockIdx.x * 8 + wrp;
    const float4* xp = (const float4*)(X + (size_t)row * DD);

    float4 v[4];
#pragma unroll
    for (int i = 0; i < 4; i++) v[i] = xp[lane + 32 * i];

    float s = 0.f;
#pragma unroll
    for (int i = 0; i < 4; i++) s += (v[i].x + v[i].y) + (v[i].z + v[i].w);
#pragma unroll
    for (int off = 16; off; off >>= 1) s += __shfl_xor_sync(0xffffffffu, s, off);
    const float mu = s * (1.f / DD);

    float q = 0.f;
#pragma unroll
    for (int i = 0; i < 4; i++) {
        const float dx = v[i].x - mu, dy = v[i].y - mu;
        const float dz = v[i].z - mu, dw = v[i].w - mu;
        q += (dx * dx + dy * dy) + (dz * dz + dw * dw);
    }
#pragma unroll
    for (int off = 16; off; off >>= 1) q += __shfl_xor_sync(0xffffffffu, q, off);
    const float rstd = rsqrtf(q * (1.f / DD) + 1e-5f);

#pragma unroll
    for (int i = 0; i < 4; i++) {
        const int c4 = lane + 32 * i;
        const float4 gv = ((const float4*)g)[c4];
        const float4 bv = ((const float4*)be)[c4];
        float4 oo;
        oo.x = (v[i].x - mu) * rstd * gv.x + bv.x;
        oo.y = (v[i].y - mu) * rstd * gv.y + bv.y;
        oo.z = (v[i].z - mu) * rstd * gv.z + bv.z;
        oo.w = (v[i].w - mu) * rstd * gv.w + bv.w;
        ((float4*)(out + (size_t)row * DD))[c4] = oo;
        if (oph) {
            uint32_t h0, m0, h1, m1;
            split_pack(oo.x, oo.y, h0, m0);
            split_pack(oo.z, oo.w, h1, m1);
            oph[(size_t)row * 256 + 2 * c4]     = h0;
            oph[(size_t)row * 256 + 2 * c4 + 1] = h1;
            opm[(size_t)row * 256 + 2 * c4]     = m0;
            opm[(size_t)row * 256 + 2 * c4 + 1] = m1;
        }
    }
}

// ---------------------------------------------------------------------------
// Launch
// ---------------------------------------------------------------------------
static void run_gemm(const uint32_t* Ah, const uint32_t* Am,
                     const uint32_t* Bh, const uint32_t* Bm,
                     const float* bias, const float* resid,
                     float* Cf, uint32_t* Ch, uint32_t* Cm,
                     int M, int N, int K, int relu)
{
    dim3 grid(N / 128, M / 64), block(256);
    tc_gemm_p<<<grid, block, SMEM_BYTES>>>(Ah, Am, Bh, Bm, bias, resid, Cf, Ch, Cm, N, K, relu);
}

extern "C" void kernel_launch(void* const* d_in, const int* in_sizes, int n_in,
                              void* d_out, int out_size)
{
    (void)in_sizes; (void)n_in; (void)out_size;
    const float* x   = (const float*)d_in[0];
    // d_in[1] = mask (deterministic causal tril) — applied analytically
    const float* wq  = (const float*)d_in[2];
    const float* bq  = (const float*)d_in[3];
    const float* wk  = (const float*)d_in[4];
    const float* bk  = (const float*)d_in[5];
    const float* wv  = (const float*)d_in[6];
    const float* bv  = (const float*)d_in[7];
    const float* wo  = (const float*)d_in[8];
    const float* bo  = (const float*)d_in[9];
    const float* w1  = (const float*)d_in[10];
    const float* b1  = (const float*)d_in[11];
    const float* w2  = (const float*)d_in[12];
    const float* b2  = (const float*)d_in[13];
    const float* g1  = (const float*)d_in[14];
    const float* be1 = (const float*)d_in[15];
    const float* g2  = (const float*)d_in[16];
    const float* be2 = (const float*)d_in[17];
    float* out = (float*)d_out;

    float *qkv, *t1, *hbuf, *bqkv;
    uint32_t *xp_h, *xp_m, *ctx_h, *ctx_m, *hp_h, *hp_m, *ffn_h, *ffn_m;
    uint32_t *wqkv_h, *wqkv_m, *wo_h, *wo_m, *w1_h, *w1_m, *w2_h, *w2_m;
    cudaGetSymbolAddress((void**)&qkv,    g_qkv);
    cudaGetSymbolAddress((void**)&t1,     g_t1);
    cudaGetSymbolAddress((void**)&hbuf,   g_h);
    cudaGetSymbolAddress((void**)&bqkv,   g_bqkv);
    cudaGetSymbolAddress((void**)&xp_h,   g_xp_h);
    cudaGetSymbolAddress((void**)&xp_m,   g_xp_m);
    cudaGetSymbolAddress((void**)&ctx_h,  g_ctx_h);
    cudaGetSymbolAddress((void**)&ctx_m,  g_ctx_m);
    cudaGetSymbolAddress((void**)&hp_h,   g_hp_h);
    cudaGetSymbolAddress((void**)&hp_m,   g_hp_m);
    cudaGetSymbolAddress((void**)&ffn_h,  g_ffn_h);
    cudaGetSymbolAddress((void**)&ffn_m,  g_ffn_m);
    cudaGetSymbolAddress((void**)&wqkv_h, g_wqkv_h);
    cudaGetSymbolAddress((void**)&wqkv_m, g_wqkv_m);
    cudaGetSymbolAddress((void**)&wo_h,   g_wo_h);
    cudaGetSymbolAddress((void**)&wo_m,   g_wo_m);
    cudaGetSymbolAddress((void**)&w1_h,   g_w1_h);
    cudaGetSymbolAddress((void**)&w1_m,   g_w1_m);
    cudaGetSymbolAddress((void**)&w2_h,   g_w2_h);
    cudaGetSymbolAddress((void**)&w2_m,   g_w2_m);

    cudaFuncSetAttribute(tc_gemm_p, cudaFuncAttributeMaxDynamicSharedMemorySize, SMEM_BYTES);
    cudaFuncSetAttribute(attn_mma,  cudaFuncAttributeMaxDynamicSharedMemorySize, ATT_SMEM_BYTES);

    // ---- packs (3 launches) ----
    pack_all<<<6144, 256>>>(wq, wk, wv, wo, w1, w2,
                            wqkv_h, wqkv_m, wo_h, wo_m, w1_h, w1_m, w2_h, w2_m);
    pack_act<<<(MM * DD / 4) / 256, 256>>>(x, xp_h, xp_m);
    pack_bias<<<QKVS / 256, 256>>>(bq, bk, bv, bqkv);

    // ---- QKV (one combined GEMM, N=1536) ----
    run_gemm(xp_h, xp_m, wqkv_h, wqkv_m, bqkv, nullptr, qkv, nullptr, nullptr,
             MM, QKVS, DD, 0);

    // ---- attention -> packed ctx ----
    attn_mma<<<dim3(SS / 64, HH, BB), 128, ATT_SMEM_BYTES>>>(qkv, ctx_h, ctx_m);

    // ---- O-proj + residual x -> t1; LN1 -> h (fp32 + packed) ----
    run_gemm(ctx_h, ctx_m, wo_h, wo_m, bo, x, t1, nullptr, nullptr, MM, DD, DD, 0);
    ln_warp<<<MM / 8, 256>>>(t1, g1, be1, hbuf, hp_h, hp_m);

    // ---- FFN ----
    run_gemm(hp_h, hp_m, w1_h, w1_m, b1, nullptr, nullptr, ffn_h, ffn_m,
             MM, FFF, DD, 1);
    run_gemm(ffn_h, ffn_m, w2_h, w2_m, b2, hbuf, t1, nullptr, nullptr,
             MM, DD, FFF, 0);
    ln_warp<<<MM / 8, 256>>>(t1, g2, be2, out, nullptr, nullptr);
}